// round 15
// baseline (speedup 1.0000x reference)
#include <cuda_runtime.h>
#include <cuda_bf16.h>
#include <math.h>
#include <stdint.h>

#define NB 4
#define NT 1024
#define NF 128
#define ND 384
#define NDEPTH 8
#define NDI 768
#define NN 16
#define NDTR 24
#define NL 513
#define NBL (NB * NL)
#define NHEAD 256
#define XPD 56
#define NW 512
#define CH 16
#define CLEN 33

typedef __nv_bfloat16 bf16;

__device__ float g_h[NBL * ND];
__device__ float g_xz[NBL * 2 * NDI];
__device__ float g_xc[NBL * NDI];
__device__ float g_xdbl[NBL * XPD];
__device__ float g_dt[NBL * NDI];
__device__ float g_part[2 * NBL * ND];
__device__ float g_sc_a[NB * CH * NDI * NN];
__device__ float g_sc_s[NB * CH * NDI * NN];
__device__ float g_sc_i[NB * CH * NDI * NN];

__device__ __align__(16) bf16 g_pm_h[2048 * 256];
__device__ __align__(16) bf16 g_pm_l[2048 * 256];
__device__ __align__(16) bf16 g_hn_h[NBL * ND];
__device__ __align__(16) bf16 g_hn_l[NBL * ND];
__device__ __align__(16) bf16 g_xc_h[NBL * NDI];
__device__ __align__(16) bf16 g_xc_l[NBL * NDI];
__device__ __align__(16) bf16 g_xd_h[NBL * XPD];
__device__ __align__(16) bf16 g_xd_l[NBL * XPD];
__device__ __align__(16) bf16 g_y_h[NBL * NDI];
__device__ __align__(16) bf16 g_y_l[NBL * NDI];
__device__ __align__(16) bf16 g_h1_h[NBL * ND];
__device__ __align__(16) bf16 g_h1_l[NBL * ND];

#define OFF_CW 0
#define N_CW (ND * 256)
#define OFF_IPW (OFF_CW + N_CW)
#define N_IPW (8 * 2 * NDI * ND)
#define OFF_XPW (OFF_IPW + N_IPW)
#define N_XPW (8 * XPD * NDI)
#define OFF_DTW (OFF_XPW + N_XPW)
#define N_DTW (8 * NDI * NDTR)
#define OFF_OPW (OFF_DTW + N_DTW)
#define N_OPW (8 * ND * NDI)
#define OFF_HW1 (OFF_OPW + N_OPW)
#define N_HW1 (ND * ND)
#define OFF_HW2 (OFF_HW1 + N_HW1)
#define N_HW2 (NHEAD * ND)
#define W_TOTAL (OFF_HW2 + N_HW2)
__device__ __align__(16) bf16 g_w_h[W_TOTAL];
__device__ __align__(16) bf16 g_w_l[W_TOTAL];

__device__ __forceinline__ uint32_t smem_u32(const void* p) {
    uint32_t a;
    asm("{ .reg .u64 t; cvta.to.shared.u64 t, %1; cvt.u32.u64 %0, t; }" : "=r"(a) : "l"(p));
    return a;
}
__device__ __forceinline__ void ldsm4(uint32_t addr, uint32_t& r0, uint32_t& r1,
                                      uint32_t& r2, uint32_t& r3) {
    asm volatile("ldmatrix.sync.aligned.m8n8.x4.shared.b16 {%0,%1,%2,%3}, [%4];"
                 : "=r"(r0), "=r"(r1), "=r"(r2), "=r"(r3) : "r"(addr));
}
__device__ __forceinline__ void mma16816(float* d, const uint32_t* a, const uint32_t* b) {
    asm volatile(
        "mma.sync.aligned.m16n8k16.row.col.f32.bf16.bf16.f32 "
        "{%0,%1,%2,%3}, {%4,%5,%6,%7}, {%8,%9}, {%0,%1,%2,%3};"
        : "+f"(d[0]), "+f"(d[1]), "+f"(d[2]), "+f"(d[3])
        : "r"(a[0]), "r"(a[1]), "r"(a[2]), "r"(a[3]), "r"(b[0]), "r"(b[1]));
}
__device__ __forceinline__ uint32_t pack_bf(float x, float y) {
    __nv_bfloat162 t = __floats2bfloat162_rn(x, y);
    return *(uint32_t*)&t;
}
__device__ __forceinline__ void cpa16(uint32_t daddr, const void* g, int sz) {
    asm volatile("cp.async.cg.shared.global [%0], [%1], 16, %2;"
                 :: "r"(daddr), "l"(g), "r"(sz) : "memory");
}
#define CP_COMMIT() asm volatile("cp.async.commit_group;" ::: "memory")
template <int Np>
__device__ __forceinline__ void cp_wait() {
    asm volatile("cp.async.wait_group %0;" :: "n"(Np) : "memory");
}

// BK=64: 64 bf16 = 128 bytes/row + 16 pad = 144 (36 words; 4-word rotation
// per row -> conflict-free 8-row ldsm phases)
#define ROWB 144
#define B64_TA (128 * ROWB)
#define B64_TB (64 * ROWB)
#define B64_BUF (2 * B64_TA + 2 * B64_TB)
#define B64_SMEM (2 * B64_BUF)

template <int EPI>
__device__ __forceinline__ void epi_store(float* C, int ldc, const float* bias,
                                          const float* aux, int M, int N,
                                          int r, int c, float v0, float v1) {
    if (r >= M || c >= N) return;
    if (EPI == 4) {
        v0 += bias[c]; v1 += bias[c + 1];
        v0 = fmaxf(v0, 0.f) + log1pf(expf(-fabsf(v0)));
        v1 = fmaxf(v1, 0.f) + log1pf(expf(-fabsf(v1)));
        *(float2*)(C + (size_t)r * ldc + c) = make_float2(v0, v1);
    } else if (EPI == 5) {
        int b = r >> 9, w = r & 511;
        v0 += bias[c] + aux[(size_t)(w + 1) * ND + c];
        v1 += bias[c + 1] + aux[(size_t)(w + 1) * ND + c + 1];
        *(float2*)(C + (size_t)(b * NL + w + 1) * ND + c) = make_float2(v0, v1);
    } else {
        *(float2*)(C + (size_t)r * ldc + c) = make_float2(v0, v1);
    }
}

// BK=64 slab load: A 128 rows x 8 chunks, B 64 rows x 8 chunks (hi+lo each)
__device__ __forceinline__ void load_slab64(uint32_t sbase, int buf,
                                            const bf16* Ah, const bf16* Al, int ldA, int M,
                                            const bf16* Wh, const bf16* Wl, int ldW, int N,
                                            int row0, int col0, int k0, int kEnd, int tid) {
    uint32_t b0 = sbase + buf * B64_BUF;
#pragma unroll
    for (int v = 0; v < 4; v++) {
        int idx = tid + v * 256;
        int r = idx >> 3, c = idx & 7;
        int gk = k0 + c * 8;
        uint32_t soff = (uint32_t)(r * ROWB + c * 16);
        int ga = row0 + r;
        int sz = (ga < M && gk < kEnd) ? 16 : 0;
        size_t go = sz ? ((size_t)ga * ldA + gk) : 0;
        cpa16(b0 + soff, Ah + go, sz);
        cpa16(b0 + B64_TA + soff, Al + go, sz);
    }
#pragma unroll
    for (int v = 0; v < 2; v++) {
        int idx = tid + v * 256;
        int r = idx >> 3, c = idx & 7;
        int gk = k0 + c * 8;
        uint32_t soff = (uint32_t)(r * ROWB + c * 16);
        int gb = col0 + r;
        int sz = (gb < N && gk < kEnd) ? 16 : 0;
        size_t go = sz ? ((size_t)gb * ldW + gk) : 0;
        cpa16(b0 + 2 * B64_TA + soff, Wh + go, sz);
        cpa16(b0 + 2 * B64_TA + B64_TB + soff, Wl + go, sz);
    }
}

// BN=64 bf16-split GEMM, BK=64, 2-stage cp.async, 2 CTAs/SM.
// Warps: 4m x 2n, warp tile 32x32.
template <int EPI>
__global__ __launch_bounds__(256, 2)
void bgemm64(const bf16* __restrict__ Ah, const bf16* __restrict__ Al, int ldA,
             const bf16* __restrict__ Wh, const bf16* __restrict__ Wl, int ldW,
             float* __restrict__ C, int ldc, long long pstride,
             const float* __restrict__ bias, const float* __restrict__ aux,
             int M, int N, int K, int kChunk) {
    extern __shared__ char sm[];
    const uint32_t sbase = smem_u32(sm);
    const int tid = threadIdx.x;
    const int wid = tid >> 5, lane = tid & 31;
    const int row0 = blockIdx.y * 128, col0 = blockIdx.x * 64;
    const int kStart = blockIdx.z * kChunk;
    const int kEnd = min(K, kStart + kChunk);
    const int nslab = (kEnd - kStart + 63) >> 6;
    if (EPI == 0) C += (long long)blockIdx.z * pstride;
    const int wm = (wid & 3) * 32;
    const int wn = (wid >> 2) * 32;

    float acc[8][4];
#pragma unroll
    for (int i = 0; i < 8; i++)
#pragma unroll
        for (int j = 0; j < 4; j++) acc[i][j] = 0.f;

    load_slab64(sbase, 0, Ah, Al, ldA, M, Wh, Wl, ldW, N, row0, col0, kStart, kEnd, tid);
    CP_COMMIT();

    for (int s = 0; s < nslab; s++) {
        if (s + 1 < nslab) {
            load_slab64(sbase, (s + 1) & 1, Ah, Al, ldA, M, Wh, Wl, ldW, N,
                        row0, col0, kStart + (s + 1) * 64, kEnd, tid);
            CP_COMMIT();
            cp_wait<1>();
        } else {
            cp_wait<0>();
        }
        __syncthreads();
        uint32_t bufb = sbase + (s & 1) * B64_BUF;
#pragma unroll
        for (int k16 = 0; k16 < 4; k16++) {
            uint32_t ah[2][4], al[2][4], bh[4][2], bl[4][2];
#pragma unroll
            for (int mt = 0; mt < 2; mt++) {
                uint32_t addr = bufb + (uint32_t)((wm + mt * 16 + (lane & 15)) * ROWB +
                                                  k16 * 32 + ((lane >> 4) * 16));
                ldsm4(addr, ah[mt][0], ah[mt][1], ah[mt][2], ah[mt][3]);
                ldsm4(addr + B64_TA, al[mt][0], al[mt][1], al[mt][2], al[mt][3]);
            }
#pragma unroll
            for (int bt = 0; bt < 2; bt++) {
                int nrow = wn + bt * 16 + ((lane >> 4) * 8) + (lane & 7);
                uint32_t addr = bufb + 2 * B64_TA +
                                (uint32_t)(nrow * ROWB + ((lane >> 3) & 1) * 16 + k16 * 32);
                ldsm4(addr, bh[2 * bt][0], bh[2 * bt][1], bh[2 * bt + 1][0], bh[2 * bt + 1][1]);
                ldsm4(addr + B64_TB, bl[2 * bt][0], bl[2 * bt][1], bl[2 * bt + 1][0],
                      bl[2 * bt + 1][1]);
            }
#pragma unroll
            for (int mt = 0; mt < 2; mt++)
#pragma unroll
                for (int nt = 0; nt < 4; nt++) mma16816(acc[mt * 4 + nt], ah[mt], bh[nt]);
#pragma unroll
            for (int mt = 0; mt < 2; mt++)
#pragma unroll
                for (int nt = 0; nt < 4; nt++) mma16816(acc[mt * 4 + nt], ah[mt], bl[nt]);
#pragma unroll
            for (int mt = 0; mt < 2; mt++)
#pragma unroll
                for (int nt = 0; nt < 4; nt++) mma16816(acc[mt * 4 + nt], al[mt], bh[nt]);
        }
        __syncthreads();
    }

    const int g = lane >> 2;
    const int tg = lane & 3;
#pragma unroll
    for (int mt = 0; mt < 2; mt++)
#pragma unroll
        for (int nt = 0; nt < 4; nt++) {
            float* d = acc[mt * 4 + nt];
            int r = row0 + wm + mt * 16 + g;
            int c = col0 + wn + nt * 8 + tg * 2;
            epi_store<EPI>(C, ldc, bias, aux, M, N, r, c, d[0], d[1]);
            epi_store<EPI>(C, ldc, bias, aux, M, N, r + 8, c, d[2], d[3]);
        }
}

template <int EPI, int OUTF, int OUTB>
__global__ void reduce_k(const float* __restrict__ part, long long pstride, int S,
                         float* __restrict__ C, const float* __restrict__ bias,
                         uint32_t* __restrict__ bhh, uint32_t* __restrict__ bll,
                         int total, int N) {
    int i4 = (blockIdx.x * blockDim.x + threadIdx.x) * 4;
    if (i4 >= total) return;
    float4 acc = *(const float4*)(part + i4);
    for (int s = 1; s < S; s++) {
        float4 p = *(const float4*)(part + (long long)s * pstride + i4);
        acc.x += p.x; acc.y += p.y; acc.z += p.z; acc.w += p.w;
    }
    if (EPI == 1) {
        float4 c = *(const float4*)(C + i4);
        acc.x += c.x; acc.y += c.y; acc.z += c.z; acc.w += c.w;
    }
    if (EPI >= 2) {
        int col = i4 % N;
        acc.x += bias[col]; acc.y += bias[col + 1];
        acc.z += bias[col + 2]; acc.w += bias[col + 3];
    }
    if (EPI == 3) {
        acc.x = fmaxf(acc.x, 0.f); acc.y = fmaxf(acc.y, 0.f);
        acc.z = fmaxf(acc.z, 0.f); acc.w = fmaxf(acc.w, 0.f);
    }
    if (OUTF) *(float4*)(C + i4) = acc;
    if (OUTB) {
        float hx = __bfloat162float(__float2bfloat16_rn(acc.x));
        float hy = __bfloat162float(__float2bfloat16_rn(acc.y));
        float hz = __bfloat162float(__float2bfloat16_rn(acc.z));
        float hw = __bfloat162float(__float2bfloat16_rn(acc.w));
        bhh[i4 / 2] = pack_bf(hx, hy);
        bhh[i4 / 2 + 1] = pack_bf(hz, hw);
        bll[i4 / 2] = pack_bf(acc.x - hx, acc.y - hy);
        bll[i4 / 2 + 1] = pack_bf(acc.z - hz, acc.w - hw);
    }
}

__global__ void fres_ln(const float* __restrict__ part, long long pstride,
                        const float* __restrict__ w, const float* __restrict__ bb,
                        float* __restrict__ h, uint32_t* __restrict__ oh,
                        uint32_t* __restrict__ ol, int rows) {
    int gw = (blockIdx.x * blockDim.x + threadIdx.x) >> 5;
    int lane = threadIdx.x & 31;
    if (gw >= rows) return;
    size_t base = (size_t)gw * ND;
    float4 hv[3];
#pragma unroll
    for (int u = 0; u < 3; u++) {
        int c = u * 128 + lane * 4;
        float4 p0 = *(const float4*)(part + base + c);
        float4 p1 = *(const float4*)(part + pstride + base + c);
        float4 hc = *(const float4*)(h + base + c);
        hv[u].x = hc.x + p0.x + p1.x;
        hv[u].y = hc.y + p0.y + p1.y;
        hv[u].z = hc.z + p0.z + p1.z;
        hv[u].w = hc.w + p0.w + p1.w;
        *(float4*)(h + base + c) = hv[u];
    }
    float s = 0.f, q = 0.f;
#pragma unroll
    for (int u = 0; u < 3; u++) {
        s += hv[u].x + hv[u].y + hv[u].z + hv[u].w;
        q += hv[u].x * hv[u].x + hv[u].y * hv[u].y + hv[u].z * hv[u].z + hv[u].w * hv[u].w;
    }
#pragma unroll
    for (int o = 16; o > 0; o >>= 1) {
        s += __shfl_xor_sync(0xffffffffu, s, o);
        q += __shfl_xor_sync(0xffffffffu, q, o);
    }
    float m = s * (1.f / ND);
    float inv = rsqrtf(q * (1.f / ND) - m * m + 1e-5f);
#pragma unroll
    for (int u = 0; u < 3; u++) {
        int c = u * 128 + lane * 4;
        float4 wv = *(const float4*)(w + c);
        float4 bv = *(const float4*)(bb + c);
        float o0 = (hv[u].x - m) * inv * wv.x + bv.x;
        float o1 = (hv[u].y - m) * inv * wv.y + bv.y;
        float o2 = (hv[u].z - m) * inv * wv.z + bv.z;
        float o3 = (hv[u].w - m) * inv * wv.w + bv.w;
        float h0 = __bfloat162float(__float2bfloat16_rn(o0));
        float h1 = __bfloat162float(__float2bfloat16_rn(o1));
        float h2 = __bfloat162float(__float2bfloat16_rn(o2));
        float h3 = __bfloat162float(__float2bfloat16_rn(o3));
        int w2 = (int)((base + c) / 2);
        oh[w2] = pack_bf(h0, h1);
        oh[w2 + 1] = pack_bf(h2, h3);
        ol[w2] = pack_bf(o0 - h0, o1 - h1);
        ol[w2 + 1] = pack_bf(o2 - h2, o3 - h3);
    }
}

__global__ void ln_kernel(const float* __restrict__ x, const float* __restrict__ w,
                          const float* __restrict__ bb, uint32_t* __restrict__ oh,
                          uint32_t* __restrict__ ol, int rows) {
    int gw = (blockIdx.x * blockDim.x + threadIdx.x) >> 5;
    int lane = threadIdx.x & 31;
    if (gw >= rows) return;
    const float* xr = x + (size_t)gw * ND;
    float4 v0 = *(const float4*)(xr + lane * 4);
    float4 v1 = *(const float4*)(xr + 128 + lane * 4);
    float4 v2 = *(const float4*)(xr + 256 + lane * 4);
    float s = v0.x + v0.y + v0.z + v0.w + v1.x + v1.y + v1.z + v1.w + v2.x + v2.y + v2.z + v2.w;
    float q = v0.x * v0.x + v0.y * v0.y + v0.z * v0.z + v0.w * v0.w +
              v1.x * v1.x + v1.y * v1.y + v1.z * v1.z + v1.w * v1.w +
              v2.x * v2.x + v2.y * v2.y + v2.z * v2.z + v2.w * v2.w;
#pragma unroll
    for (int o = 16; o > 0; o >>= 1) {
        s += __shfl_xor_sync(0xffffffffu, s, o);
        q += __shfl_xor_sync(0xffffffffu, q, o);
    }
    float m = s * (1.f / ND);
    float inv = rsqrtf(q * (1.f / ND) - m * m + 1e-5f);
#pragma unroll
    for (int u = 0; u < 3; u++) {
        int c = u * 128 + lane * 4;
        float4 v = (u == 0) ? v0 : (u == 1) ? v1 : v2;
        float4 wv = *(const float4*)(w + c);
        float4 bv = *(const float4*)(bb + c);
        float o0 = (v.x - m) * inv * wv.x + bv.x;
        float o1 = (v.y - m) * inv * wv.y + bv.y;
        float o2 = (v.z - m) * inv * wv.z + bv.z;
        float o3 = (v.w - m) * inv * wv.w + bv.w;
        float h0 = __bfloat162float(__float2bfloat16_rn(o0));
        float h1 = __bfloat162float(__float2bfloat16_rn(o1));
        float h2 = __bfloat162float(__float2bfloat16_rn(o2));
        float h3 = __bfloat162float(__float2bfloat16_rn(o3));
        int w2 = (int)(((size_t)gw * ND + c) / 2);
        oh[w2] = pack_bf(h0, h1);
        oh[w2 + 1] = pack_bf(h2, h3);
        ol[w2] = pack_bf(o0 - h0, o1 - h1);
        ol[w2 + 1] = pack_bf(o2 - h2, o3 - h3);
    }
}

__global__ void split_a(const float* __restrict__ ipw, const float* __restrict__ opw,
                        bf16* __restrict__ hi, bf16* __restrict__ lo) {
    int n = N_IPW + N_OPW;
    for (int i = blockIdx.x * blockDim.x + threadIdx.x; i < n; i += gridDim.x * blockDim.x) {
        float v;
        int o;
        if (i < N_IPW) { v = ipw[i]; o = OFF_IPW + i; }
        else { v = opw[i - N_IPW]; o = OFF_OPW + (i - N_IPW); }
        bf16 h = __float2bfloat16_rn(v);
        hi[o] = h;
        lo[o] = __float2bfloat16_rn(v - __bfloat162float(h));
    }
}
__global__ void split_b(const float* __restrict__ cw, const float* __restrict__ xpw,
                        const float* __restrict__ dtw, const float* __restrict__ hw1,
                        const float* __restrict__ hw2, bf16* __restrict__ hi,
                        bf16* __restrict__ lo) {
    int n = N_CW + N_XPW + N_DTW + N_HW1 + N_HW2;
    for (int i = blockIdx.x * blockDim.x + threadIdx.x; i < n; i += gridDim.x * blockDim.x) {
        float v;
        int o;
        int j = i;
        if (j < N_CW) { v = cw[j]; o = OFF_CW + j; }
        else if ((j -= N_CW) < N_XPW) { v = xpw[j]; o = OFF_XPW + j; }
        else if ((j -= N_XPW) < N_DTW) { v = dtw[j]; o = OFF_DTW + j; }
        else if ((j -= N_DTW) < N_HW1) { v = hw1[j]; o = OFF_HW1 + j; }
        else { j -= N_HW1; v = hw2[j]; o = OFF_HW2 + j; }
        bf16 h = __float2bfloat16_rn(v);
        hi[o] = h;
        lo[o] = __float2bfloat16_rn(v - __bfloat162float(h));
    }
}

__global__ void gather_patches(const float* __restrict__ x, bf16* __restrict__ ph,
                               bf16* __restrict__ pl, const float* __restrict__ cls,
                               const float* __restrict__ pos, float* __restrict__ h) {
    int idx = blockIdx.x * blockDim.x + threadIdx.x;
    if (idx >= NB * NW * 256) return;
    if (idx < NB * ND) {
        int b = idx / ND, d = idx % ND;
        h[(size_t)(b * NL) * ND + d] = cls[d] + pos[d];
    }
    int k = idx & 255;
    int bw = idx >> 8;
    int w = bw & (NW - 1);
    int b = bw >> 9;
    float v = x[b * (NT * NF) + (2 * w + (k & 1)) * NF + (k >> 1)];
    bf16 hh = __float2bfloat16_rn(v);
    ph[idx] = hh;
    pl[idx] = __float2bfloat16_rn(v - __bfloat162float(hh));
}

__global__ void conv1d_silu_kernel(const float* __restrict__ xz, const float* __restrict__ w,
                                   const float* __restrict__ bconv, float* __restrict__ xc,
                                   bf16* __restrict__ xch, bf16* __restrict__ xcl) {
    int c = blockIdx.x * blockDim.x + threadIdx.x;
    int l0 = blockIdx.y * 4;
    int b = blockIdx.z;
    float v[7];
#pragma unroll
    for (int j = 0; j < 7; j++) {
        int l = l0 - 3 + j;
        v[j] = (l >= 0 && l < NL) ? xz[((size_t)(b * NL + l)) * (2 * NDI) + c] : 0.f;
    }
    float4 wt = *(const float4*)(w + c * 4);
    float bc = bconv[c];
#pragma unroll
    for (int t = 0; t < 4; t++) {
        int l = l0 + t;
        if (l >= NL) break;
        float a = bc;
        a = fmaf(v[t], wt.x, a);
        a = fmaf(v[t + 1], wt.y, a);
        a = fmaf(v[t + 2], wt.z, a);
        a = fmaf(v[t + 3], wt.w, a);
        float o = a / (1.f + __expf(-a));
        size_t idx = ((size_t)(b * NL + l)) * NDI + c;
        xc[idx] = o;
        bf16 hh = __float2bfloat16_rn(o);
        xch[idx] = hh;
        xcl[idx] = __float2bfloat16_rn(o - __bfloat162float(hh));
    }
}

__global__ void scan_a(const float* __restrict__ dt, const float* __restrict__ xc,
                       const float* __restrict__ xdbl, const float* __restrict__ Alog,
                       float* __restrict__ ao, float* __restrict__ so) {
    int lane = threadIdx.x & 31;
    int warp = threadIdx.x >> 5;
    int n = lane & 15;
    int ch = lane >> 4;
    int b = blockIdx.y;
    int c = blockIdx.z;
    int d = blockIdx.x * 16 + warp * 2 + ch;
    const float negA = -__expf(Alog[d * NN + n]);
    float ap = 1.f, s = 0.f;
    int t0 = c * CLEN, t1 = min(NL, t0 + CLEN);
    for (int t = t0; t < t1; t++) {
        int row = b * NL + t;
        float dtv = dt[(size_t)row * NDI + d];
        float xv = xc[(size_t)row * NDI + d];
        float Bn = xdbl[(size_t)row * XPD + NDTR + n];
        float a = __expf(dtv * negA);
        s = fmaf(a, s, dtv * Bn * xv);
        ap *= a;
    }
    int o = ((b * CH + c) * NDI + d) * NN + n;
    ao[o] = ap;
    so[o] = s;
}

__global__ void scan_b(const float* __restrict__ ao, const float* __restrict__ so,
                       float* __restrict__ io) {
    int idx = blockIdx.x * blockDim.x + threadIdx.x;
    if (idx >= NB * NDI * NN) return;
    int b = idx / (NDI * NN);
    int j = idx % (NDI * NN);
    float S = 0.f;
    for (int c = 0; c < CH; c++) {
        int o = (b * CH + c) * NDI * NN + j;
        io[o] = S;
        S = so[o] + ao[o] * S;
    }
}

__global__ void scan_c(const float* __restrict__ dt, const float* __restrict__ xc,
                       const float* __restrict__ xdbl, const float* __restrict__ xz,
                       const float* __restrict__ Alog, const float* __restrict__ Dsk,
                       const float* __restrict__ io, bf16* __restrict__ yh,
                       bf16* __restrict__ yl) {
    int lane = threadIdx.x & 31;
    int warp = threadIdx.x >> 5;
    int n = lane & 15;
    int ch = lane >> 4;
    int b = blockIdx.y;
    int c = blockIdx.z;
    int d = blockIdx.x * 16 + warp * 2 + ch;
    const float negA = -__expf(Alog[d * NN + n]);
    const float dsk = Dsk[d];
    float s = io[((b * CH + c) * NDI + d) * NN + n];
    int t0 = c * CLEN, t1 = min(NL, t0 + CLEN);
    for (int t = t0; t < t1; t++) {
        int row = b * NL + t;
        float dtv = dt[(size_t)row * NDI + d];
        float xv = xc[(size_t)row * NDI + d];
        float Bn = xdbl[(size_t)row * XPD + NDTR + n];
        float Cn = xdbl[(size_t)row * XPD + NDTR + NN + n];
        float a = __expf(dtv * negA);
        s = fmaf(a, s, dtv * Bn * xv);
        float p = s * Cn;
        p += __shfl_xor_sync(0xffffffffu, p, 8, 16);
        p += __shfl_xor_sync(0xffffffffu, p, 4, 16);
        p += __shfl_xor_sync(0xffffffffu, p, 2, 16);
        p += __shfl_xor_sync(0xffffffffu, p, 1, 16);
        if (n == 0) {
            float yv = fmaf(dsk, xv, p);
            float zv = xz[(size_t)row * (2 * NDI) + NDI + d];
            yv *= zv / (1.f + __expf(-zv));
            bf16 hh = __float2bfloat16_rn(yv);
            yh[(size_t)row * NDI + d] = hh;
            yl[(size_t)row * NDI + d] = __float2bfloat16_rn(yv - __bfloat162float(hh));
        }
    }
}

static inline int cdiv(int a, int b) { return (a + b - 1) / b; }

extern "C" void kernel_launch(void* const* d_in, const int* in_sizes, int n_in,
                              void* d_out, int out_size) {
    const float* x = (const float*)d_in[0];
    const float* conv_w = (const float*)d_in[1];
    const float* conv_b = (const float*)d_in[2];
    const float* cls_tok = (const float*)d_in[3];
    const float* pos = (const float*)d_in[4];
    const float* norm_w = (const float*)d_in[5];
    const float* norm_b = (const float*)d_in[6];
    const float* ipw = (const float*)d_in[7];
    const float* c1w = (const float*)d_in[8];
    const float* c1b = (const float*)d_in[9];
    const float* xpw = (const float*)d_in[10];
    const float* dtw = (const float*)d_in[11];
    const float* dtb = (const float*)d_in[12];
    const float* Alog = (const float*)d_in[13];
    const float* Dsk = (const float*)d_in[14];
    const float* opw = (const float*)d_in[15];
    const float* nfw = (const float*)d_in[16];
    const float* nfb = (const float*)d_in[17];
    const float* hw1 = (const float*)d_in[18];
    const float* hb1 = (const float*)d_in[19];
    const float* hw2 = (const float*)d_in[20];
    const float* hb2 = (const float*)d_in[21];

    float *h, *xz, *xc, *xdbl, *dt, *part, *sca, *scs, *sci;
    bf16 *pmh, *pml, *hnh, *hnl, *xch, *xcl, *xdh, *xdl, *yh, *yl, *h1h, *h1l, *wh, *wl;
    cudaGetSymbolAddress((void**)&h, g_h);
    cudaGetSymbolAddress((void**)&xz, g_xz);
    cudaGetSymbolAddress((void**)&xc, g_xc);
    cudaGetSymbolAddress((void**)&xdbl, g_xdbl);
    cudaGetSymbolAddress((void**)&dt, g_dt);
    cudaGetSymbolAddress((void**)&part, g_part);
    cudaGetSymbolAddress((void**)&sca, g_sc_a);
    cudaGetSymbolAddress((void**)&scs, g_sc_s);
    cudaGetSymbolAddress((void**)&sci, g_sc_i);
    cudaGetSymbolAddress((void**)&pmh, g_pm_h);
    cudaGetSymbolAddress((void**)&pml, g_pm_l);
    cudaGetSymbolAddress((void**)&hnh, g_hn_h);
    cudaGetSymbolAddress((void**)&hnl, g_hn_l);
    cudaGetSymbolAddress((void**)&xch, g_xc_h);
    cudaGetSymbolAddress((void**)&xcl, g_xc_l);
    cudaGetSymbolAddress((void**)&xdh, g_xd_h);
    cudaGetSymbolAddress((void**)&xdl, g_xd_l);
    cudaGetSymbolAddress((void**)&yh, g_y_h);
    cudaGetSymbolAddress((void**)&yl, g_y_l);
    cudaGetSymbolAddress((void**)&h1h, g_h1_h);
    cudaGetSymbolAddress((void**)&h1l, g_h1_l);
    cudaGetSymbolAddress((void**)&wh, g_w_h);
    cudaGetSymbolAddress((void**)&wl, g_w_l);

    cudaFuncSetAttribute(bgemm64<0>, cudaFuncAttributeMaxDynamicSharedMemorySize, B64_SMEM);
    cudaFuncSetAttribute(bgemm64<4>, cudaFuncAttributeMaxDynamicSharedMemorySize, B64_SMEM);
    cudaFuncSetAttribute(bgemm64<5>, cudaFuncAttributeMaxDynamicSharedMemorySize, B64_SMEM);

    split_a<<<2048, 256>>>(ipw, opw, wh, wl);
    split_b<<<1024, 256>>>(conv_w, xpw, dtw, hw1, hw2, wh, wl);
    gather_patches<<<cdiv(NB * NW * 256, 256), 256>>>(x, pmh, pml, cls_tok, pos, h);
    bgemm64<5><<<dim3(6, 16, 1), 256, B64_SMEM>>>(
        pmh, pml, 256, wh + OFF_CW, wl + OFF_CW, 256, h, ND, 0, conv_b, pos,
        2048, ND, 256, 256);
    ln_kernel<<<cdiv(NBL * 32, 256), 256>>>(h, norm_w, norm_b,
                                            (uint32_t*)hnh, (uint32_t*)hnl, NBL);

    for (int i = 0; i < NDEPTH; i++) {
        bgemm64<0><<<dim3(24, 17, 1), 256, B64_SMEM>>>(
            hnh, hnl, ND, wh + OFF_IPW + (size_t)i * 2 * NDI * ND,
            wl + OFF_IPW + (size_t)i * 2 * NDI * ND, ND, xz, 2 * NDI, 0,
            nullptr, nullptr, NBL, 2 * NDI, ND, ND);
        conv1d_silu_kernel<<<dim3(3, cdiv(NL, 4), NB), 256>>>(
            xz, c1w + (size_t)i * NDI * 4, c1b + (size_t)i * NDI, xc, xch, xcl);
        bgemm64<0><<<dim3(1, 17, 6), 256, B64_SMEM>>>(
            xch, xcl, NDI, wh + OFF_XPW + (size_t)i * XPD * NDI,
            wl + OFF_XPW + (size_t)i * XPD * NDI, NDI, part, XPD,
            (long long)NBL * XPD, nullptr, nullptr, NBL, XPD, NDI, 128);
        reduce_k<0, 1, 1><<<cdiv(NBL * XPD / 4, 256), 256>>>(
            part, (long long)NBL * XPD, 6, xdbl, nullptr,
            (uint32_t*)xdh, (uint32_t*)xdl, NBL * XPD, XPD);
        bgemm64<4><<<dim3(12, 17, 1), 256, B64_SMEM>>>(
            xdh, xdl, XPD, wh + OFF_DTW + (size_t)i * NDI * NDTR,
            wl + OFF_DTW + (size_t)i * NDI * NDTR, NDTR, dt, NDI, 0,
            dtb + (size_t)i * NDI, nullptr, NBL, NDI, NDTR, NDTR);
        scan_a<<<dim3(NDI / 16, NB, CH), 256>>>(dt, xc, xdbl,
                                                Alog + (size_t)i * NDI * NN, sca, scs);
        scan_b<<<cdiv(NB * NDI * NN, 256), 256>>>(sca, scs, sci);
        scan_c<<<dim3(NDI / 16, NB, CH), 256>>>(dt, xc, xdbl, xz,
                                                Alog + (size_t)i * NDI * NN,
                                                Dsk + (size_t)i * NDI, sci, yh, yl);
        bgemm64<0><<<dim3(6, 17, 2), 256, B64_SMEM>>>(
            yh, yl, NDI, wh + OFF_OPW + (size_t)i * ND * NDI,
            wl + OFF_OPW + (size_t)i * ND * NDI, NDI, part, ND,
            (long long)NBL * ND, nullptr, nullptr, NBL, ND, NDI, 384);
        const float* lw = (i + 1 < NDEPTH) ? (norm_w + (i + 1) * ND) : nfw;
        const float* lb = (i + 1 < NDEPTH) ? (norm_b + (i + 1) * ND) : nfb;
        fres_ln<<<cdiv(NBL * 32, 256), 256>>>(part, (long long)NBL * ND, lw, lb, h,
                                              (uint32_t*)hnh, (uint32_t*)hnl, NBL);
    }

    bgemm64<0><<<dim3(6, 17, 2), 256, B64_SMEM>>>(
        hnh, hnl, ND, wh + OFF_HW1, wl + OFF_HW1, ND, part, ND,
        (long long)NBL * ND, nullptr, nullptr, NBL, ND, ND, 192);
    reduce_k<3, 0, 1><<<cdiv(NBL * ND / 4, 256), 256>>>(
        part, (long long)NBL * ND, 2, nullptr, hb1,
        (uint32_t*)h1h, (uint32_t*)h1l, NBL * ND, ND);
    bgemm64<0><<<dim3(4, 17, 2), 256, B64_SMEM>>>(
        h1h, h1l, ND, wh + OFF_HW2, wl + OFF_HW2, ND, part, NHEAD,
        (long long)NBL * NHEAD, nullptr, nullptr, NBL, NHEAD, ND, 192);
    reduce_k<2, 1, 0><<<cdiv(NBL * NHEAD / 4, 256), 256>>>(
        part, (long long)NBL * NHEAD, 2, (float*)d_out, hb2, nullptr, nullptr,
        NBL * NHEAD, NHEAD);
}

// round 16
// speedup vs baseline: 1.0528x; 1.0528x over previous
#include <cuda_runtime.h>
#include <cuda_bf16.h>
#include <math.h>
#include <stdint.h>

#define NB 4
#define NT 1024
#define NF 128
#define ND 384
#define NDEPTH 8
#define NDI 768
#define NN 16
#define NDTR 24
#define NL 513
#define NBL (NB * NL)
#define NHEAD 256
#define XPD 56
#define NW 512
#define CH 16
#define CLEN 33

typedef __nv_bfloat16 bf16;

__device__ float g_h[NBL * ND];
__device__ float g_xz[NBL * 2 * NDI];
__device__ float g_xc[NBL * NDI];
__device__ float g_xdbl[NBL * XPD];
__device__ float g_dt[NBL * NDI];
__device__ float g_part[2 * NBL * ND];
__device__ float g_sc_a[NB * CH * NDI * NN];
__device__ float g_sc_s[NB * CH * NDI * NN];

__device__ __align__(16) bf16 g_pm_h[2048 * 256];
__device__ __align__(16) bf16 g_pm_l[2048 * 256];
__device__ __align__(16) bf16 g_hn_h[NBL * ND];
__device__ __align__(16) bf16 g_hn_l[NBL * ND];
__device__ __align__(16) bf16 g_xc_h[NBL * NDI];
__device__ __align__(16) bf16 g_xc_l[NBL * NDI];
__device__ __align__(16) bf16 g_xd_h[NBL * XPD];
__device__ __align__(16) bf16 g_xd_l[NBL * XPD];
__device__ __align__(16) bf16 g_y_h[NBL * NDI];
__device__ __align__(16) bf16 g_y_l[NBL * NDI];
__device__ __align__(16) bf16 g_h1_h[NBL * ND];
__device__ __align__(16) bf16 g_h1_l[NBL * ND];

#define OFF_CW 0
#define N_CW (ND * 256)
#define OFF_IPW (OFF_CW + N_CW)
#define N_IPW (8 * 2 * NDI * ND)
#define OFF_XPW (OFF_IPW + N_IPW)
#define N_XPW (8 * XPD * NDI)
#define OFF_DTW (OFF_XPW + N_XPW)
#define N_DTW (8 * NDI * NDTR)
#define OFF_OPW (OFF_DTW + N_DTW)
#define N_OPW (8 * ND * NDI)
#define OFF_HW1 (OFF_OPW + N_OPW)
#define N_HW1 (ND * ND)
#define OFF_HW2 (OFF_HW1 + N_HW1)
#define N_HW2 (NHEAD * ND)
#define W_TOTAL (OFF_HW2 + N_HW2)
__device__ __align__(16) bf16 g_w_h[W_TOTAL];
__device__ __align__(16) bf16 g_w_l[W_TOTAL];

__device__ __forceinline__ uint32_t smem_u32(const void* p) {
    uint32_t a;
    asm("{ .reg .u64 t; cvta.to.shared.u64 t, %1; cvt.u32.u64 %0, t; }" : "=r"(a) : "l"(p));
    return a;
}
__device__ __forceinline__ void ldsm4(uint32_t addr, uint32_t& r0, uint32_t& r1,
                                      uint32_t& r2, uint32_t& r3) {
    asm volatile("ldmatrix.sync.aligned.m8n8.x4.shared.b16 {%0,%1,%2,%3}, [%4];"
                 : "=r"(r0), "=r"(r1), "=r"(r2), "=r"(r3) : "r"(addr));
}
__device__ __forceinline__ void mma16816(float* d, const uint32_t* a, const uint32_t* b) {
    asm volatile(
        "mma.sync.aligned.m16n8k16.row.col.f32.bf16.bf16.f32 "
        "{%0,%1,%2,%3}, {%4,%5,%6,%7}, {%8,%9}, {%0,%1,%2,%3};"
        : "+f"(d[0]), "+f"(d[1]), "+f"(d[2]), "+f"(d[3])
        : "r"(a[0]), "r"(a[1]), "r"(a[2]), "r"(a[3]), "r"(b[0]), "r"(b[1]));
}
__device__ __forceinline__ uint32_t pack_bf(float x, float y) {
    __nv_bfloat162 t = __floats2bfloat162_rn(x, y);
    return *(uint32_t*)&t;
}
__device__ __forceinline__ void cpa16(uint32_t daddr, const void* g, int sz) {
    asm volatile("cp.async.cg.shared.global [%0], [%1], 16, %2;"
                 :: "r"(daddr), "l"(g), "r"(sz) : "memory");
}
#define CP_COMMIT() asm volatile("cp.async.commit_group;" ::: "memory")
template <int Np>
__device__ __forceinline__ void cp_wait() {
    asm volatile("cp.async.wait_group %0;" :: "n"(Np) : "memory");
}

#define ROWB 80
#define B64_TA (128 * ROWB)
#define B64_TB (64 * ROWB)
#define B64_BUF (2 * B64_TA + 2 * B64_TB)
#define B64_SMEM (3 * B64_BUF)

template <int EPI>
__device__ __forceinline__ void epi_store(float* C, int ldc, const float* bias,
                                          const float* aux, int M, int N,
                                          int r, int c, float v0, float v1) {
    if (r >= M || c >= N) return;
    if (EPI == 4) {
        v0 += bias[c]; v1 += bias[c + 1];
        v0 = fmaxf(v0, 0.f) + log1pf(expf(-fabsf(v0)));
        v1 = fmaxf(v1, 0.f) + log1pf(expf(-fabsf(v1)));
        *(float2*)(C + (size_t)r * ldc + c) = make_float2(v0, v1);
    } else if (EPI == 5) {
        int b = r >> 9, w = r & 511;
        v0 += bias[c] + aux[(size_t)(w + 1) * ND + c];
        v1 += bias[c + 1] + aux[(size_t)(w + 1) * ND + c + 1];
        *(float2*)(C + (size_t)(b * NL + w + 1) * ND + c) = make_float2(v0, v1);
    } else {
        *(float2*)(C + (size_t)r * ldc + c) = make_float2(v0, v1);
    }
}

__device__ __forceinline__ void load_slab64(uint32_t sbase, int buf,
                                            const bf16* Ah, const bf16* Al, int ldA, int M,
                                            const bf16* Wh, const bf16* Wl, int ldW, int N,
                                            int row0, int col0, int k0, int kEnd, int tid) {
    uint32_t b0 = sbase + buf * B64_BUF;
#pragma unroll
    for (int v = 0; v < 2; v++) {
        int idx = tid + v * 256;
        int r = idx >> 2, c = idx & 3;
        int gk = k0 + c * 8;
        uint32_t soff = (uint32_t)(r * ROWB + c * 16);
        int ga = row0 + r;
        int sz = (ga < M && gk < kEnd) ? 16 : 0;
        size_t go = sz ? ((size_t)ga * ldA + gk) : 0;
        cpa16(b0 + soff, Ah + go, sz);
        cpa16(b0 + B64_TA + soff, Al + go, sz);
    }
    {
        int r = tid >> 2, c = tid & 3;
        int gk = k0 + c * 8;
        uint32_t soff = (uint32_t)(r * ROWB + c * 16);
        int gb = col0 + r;
        int sz = (gb < N && gk < kEnd) ? 16 : 0;
        size_t go = sz ? ((size_t)gb * ldW + gk) : 0;
        cpa16(b0 + 2 * B64_TA + soff, Wh + go, sz);
        cpa16(b0 + 2 * B64_TA + B64_TB + soff, Wl + go, sz);
    }
}

// BN=64 bf16-split GEMM, BK=32, 3-stage cp.async pipeline, 2 CTAs/SM.
// Warps: 4m x 2n, warp tile 32x32.
template <int EPI>
__global__ __launch_bounds__(256, 2)
void bgemm64(const bf16* __restrict__ Ah, const bf16* __restrict__ Al, int ldA,
             const bf16* __restrict__ Wh, const bf16* __restrict__ Wl, int ldW,
             float* __restrict__ C, int ldc, long long pstride,
             const float* __restrict__ bias, const float* __restrict__ aux,
             int M, int N, int K, int kChunk) {
    extern __shared__ char sm[];
    const uint32_t sbase = smem_u32(sm);
    const int tid = threadIdx.x;
    const int wid = tid >> 5, lane = tid & 31;
    const int row0 = blockIdx.y * 128, col0 = blockIdx.x * 64;
    const int kStart = blockIdx.z * kChunk;
    const int kEnd = min(K, kStart + kChunk);
    const int nslab = (kEnd - kStart + 31) >> 5;
    if (EPI == 0) C += (long long)blockIdx.z * pstride;
    const int wm = (wid & 3) * 32;
    const int wn = (wid >> 2) * 32;

    float acc[8][4];
#pragma unroll
    for (int i = 0; i < 8; i++)
#pragma unroll
        for (int j = 0; j < 4; j++) acc[i][j] = 0.f;

    load_slab64(sbase, 0, Ah, Al, ldA, M, Wh, Wl, ldW, N, row0, col0, kStart, kEnd, tid);
    CP_COMMIT();
    if (nslab > 1)
        load_slab64(sbase, 1, Ah, Al, ldA, M, Wh, Wl, ldW, N,
                    row0, col0, kStart + 32, kEnd, tid);
    CP_COMMIT();

    int cm = 0, ld = 2;
    for (int s = 0; s < nslab; s++) {
        cp_wait<1>();
        __syncthreads();
        uint32_t bufb = sbase + cm * B64_BUF;
#pragma unroll
        for (int k16 = 0; k16 < 2; k16++) {
            uint32_t ah[2][4], al[2][4], bh[4][2], bl[4][2];
#pragma unroll
            for (int mt = 0; mt < 2; mt++) {
                uint32_t addr = bufb + (uint32_t)((wm + mt * 16 + (lane & 15)) * ROWB +
                                                  k16 * 32 + ((lane >> 4) * 16));
                ldsm4(addr, ah[mt][0], ah[mt][1], ah[mt][2], ah[mt][3]);
                ldsm4(addr + B64_TA, al[mt][0], al[mt][1], al[mt][2], al[mt][3]);
            }
#pragma unroll
            for (int bt = 0; bt < 2; bt++) {
                int nrow = wn + bt * 16 + ((lane >> 4) * 8) + (lane & 7);
                uint32_t addr = bufb + 2 * B64_TA +
                                (uint32_t)(nrow * ROWB + ((lane >> 3) & 1) * 16 + k16 * 32);
                ldsm4(addr, bh[2 * bt][0], bh[2 * bt][1], bh[2 * bt + 1][0], bh[2 * bt + 1][1]);
                ldsm4(addr + B64_TB, bl[2 * bt][0], bl[2 * bt][1], bl[2 * bt + 1][0],
                      bl[2 * bt + 1][1]);
            }
#pragma unroll
            for (int mt = 0; mt < 2; mt++)
#pragma unroll
                for (int nt = 0; nt < 4; nt++) mma16816(acc[mt * 4 + nt], ah[mt], bh[nt]);
#pragma unroll
            for (int mt = 0; mt < 2; mt++)
#pragma unroll
                for (int nt = 0; nt < 4; nt++) mma16816(acc[mt * 4 + nt], ah[mt], bl[nt]);
#pragma unroll
            for (int mt = 0; mt < 2; mt++)
#pragma unroll
                for (int nt = 0; nt < 4; nt++) mma16816(acc[mt * 4 + nt], al[mt], bh[nt]);
        }
        if (s + 2 < nslab)
            load_slab64(sbase, ld, Ah, Al, ldA, M, Wh, Wl, ldW, N,
                        row0, col0, kStart + (s + 2) * 32, kEnd, tid);
        CP_COMMIT();
        cm = (cm == 2) ? 0 : cm + 1;
        ld = (ld == 2) ? 0 : ld + 1;
    }

    const int g = lane >> 2;
    const int tg = lane & 3;
#pragma unroll
    for (int mt = 0; mt < 2; mt++)
#pragma unroll
        for (int nt = 0; nt < 4; nt++) {
            float* d = acc[mt * 4 + nt];
            int r = row0 + wm + mt * 16 + g;
            int c = col0 + wn + nt * 8 + tg * 2;
            epi_store<EPI>(C, ldc, bias, aux, M, N, r, c, d[0], d[1]);
            epi_store<EPI>(C, ldc, bias, aux, M, N, r + 8, c, d[2], d[3]);
        }
}

template <int EPI, int OUTF, int OUTB>
__global__ void reduce_k(const float* __restrict__ part, long long pstride, int S,
                         float* __restrict__ C, const float* __restrict__ bias,
                         uint32_t* __restrict__ bhh, uint32_t* __restrict__ bll,
                         int total, int N) {
    int i4 = (blockIdx.x * blockDim.x + threadIdx.x) * 4;
    if (i4 >= total) return;
    float4 acc = *(const float4*)(part + i4);
    for (int s = 1; s < S; s++) {
        float4 p = *(const float4*)(part + (long long)s * pstride + i4);
        acc.x += p.x; acc.y += p.y; acc.z += p.z; acc.w += p.w;
    }
    if (EPI == 1) {
        float4 c = *(const float4*)(C + i4);
        acc.x += c.x; acc.y += c.y; acc.z += c.z; acc.w += c.w;
    }
    if (EPI >= 2) {
        int col = i4 % N;
        acc.x += bias[col]; acc.y += bias[col + 1];
        acc.z += bias[col + 2]; acc.w += bias[col + 3];
    }
    if (EPI == 3) {
        acc.x = fmaxf(acc.x, 0.f); acc.y = fmaxf(acc.y, 0.f);
        acc.z = fmaxf(acc.z, 0.f); acc.w = fmaxf(acc.w, 0.f);
    }
    if (OUTF) *(float4*)(C + i4) = acc;
    if (OUTB) {
        float hx = __bfloat162float(__float2bfloat16_rn(acc.x));
        float hy = __bfloat162float(__float2bfloat16_rn(acc.y));
        float hz = __bfloat162float(__float2bfloat16_rn(acc.z));
        float hw = __bfloat162float(__float2bfloat16_rn(acc.w));
        bhh[i4 / 2] = pack_bf(hx, hy);
        bhh[i4 / 2 + 1] = pack_bf(hz, hw);
        bll[i4 / 2] = pack_bf(acc.x - hx, acc.y - hy);
        bll[i4 / 2 + 1] = pack_bf(acc.z - hz, acc.w - hw);
    }
}

__global__ void fres_ln(const float* __restrict__ part, long long pstride,
                        const float* __restrict__ w, const float* __restrict__ bb,
                        float* __restrict__ h, uint32_t* __restrict__ oh,
                        uint32_t* __restrict__ ol, int rows) {
    int gw = (blockIdx.x * blockDim.x + threadIdx.x) >> 5;
    int lane = threadIdx.x & 31;
    if (gw >= rows) return;
    size_t base = (size_t)gw * ND;
    float4 hv[3];
#pragma unroll
    for (int u = 0; u < 3; u++) {
        int c = u * 128 + lane * 4;
        float4 p0 = *(const float4*)(part + base + c);
        float4 p1 = *(const float4*)(part + pstride + base + c);
        float4 hc = *(const float4*)(h + base + c);
        hv[u].x = hc.x + p0.x + p1.x;
        hv[u].y = hc.y + p0.y + p1.y;
        hv[u].z = hc.z + p0.z + p1.z;
        hv[u].w = hc.w + p0.w + p1.w;
        *(float4*)(h + base + c) = hv[u];
    }
    float s = 0.f, q = 0.f;
#pragma unroll
    for (int u = 0; u < 3; u++) {
        s += hv[u].x + hv[u].y + hv[u].z + hv[u].w;
        q += hv[u].x * hv[u].x + hv[u].y * hv[u].y + hv[u].z * hv[u].z + hv[u].w * hv[u].w;
    }
#pragma unroll
    for (int o = 16; o > 0; o >>= 1) {
        s += __shfl_xor_sync(0xffffffffu, s, o);
        q += __shfl_xor_sync(0xffffffffu, q, o);
    }
    float m = s * (1.f / ND);
    float inv = rsqrtf(q * (1.f / ND) - m * m + 1e-5f);
#pragma unroll
    for (int u = 0; u < 3; u++) {
        int c = u * 128 + lane * 4;
        float4 wv = *(const float4*)(w + c);
        float4 bv = *(const float4*)(bb + c);
        float o0 = (hv[u].x - m) * inv * wv.x + bv.x;
        float o1 = (hv[u].y - m) * inv * wv.y + bv.y;
        float o2 = (hv[u].z - m) * inv * wv.z + bv.z;
        float o3 = (hv[u].w - m) * inv * wv.w + bv.w;
        float h0 = __bfloat162float(__float2bfloat16_rn(o0));
        float h1 = __bfloat162float(__float2bfloat16_rn(o1));
        float h2 = __bfloat162float(__float2bfloat16_rn(o2));
        float h3 = __bfloat162float(__float2bfloat16_rn(o3));
        int w2 = (int)((base + c) / 2);
        oh[w2] = pack_bf(h0, h1);
        oh[w2 + 1] = pack_bf(h2, h3);
        ol[w2] = pack_bf(o0 - h0, o1 - h1);
        ol[w2 + 1] = pack_bf(o2 - h2, o3 - h3);
    }
}

__global__ void ln_kernel(const float* __restrict__ x, const float* __restrict__ w,
                          const float* __restrict__ bb, uint32_t* __restrict__ oh,
                          uint32_t* __restrict__ ol, int rows) {
    int gw = (blockIdx.x * blockDim.x + threadIdx.x) >> 5;
    int lane = threadIdx.x & 31;
    if (gw >= rows) return;
    const float* xr = x + (size_t)gw * ND;
    float4 v0 = *(const float4*)(xr + lane * 4);
    float4 v1 = *(const float4*)(xr + 128 + lane * 4);
    float4 v2 = *(const float4*)(xr + 256 + lane * 4);
    float s = v0.x + v0.y + v0.z + v0.w + v1.x + v1.y + v1.z + v1.w + v2.x + v2.y + v2.z + v2.w;
    float q = v0.x * v0.x + v0.y * v0.y + v0.z * v0.z + v0.w * v0.w +
              v1.x * v1.x + v1.y * v1.y + v1.z * v1.z + v1.w * v1.w +
              v2.x * v2.x + v2.y * v2.y + v2.z * v2.z + v2.w * v2.w;
#pragma unroll
    for (int o = 16; o > 0; o >>= 1) {
        s += __shfl_xor_sync(0xffffffffu, s, o);
        q += __shfl_xor_sync(0xffffffffu, q, o);
    }
    float m = s * (1.f / ND);
    float inv = rsqrtf(q * (1.f / ND) - m * m + 1e-5f);
#pragma unroll
    for (int u = 0; u < 3; u++) {
        int c = u * 128 + lane * 4;
        float4 v = (u == 0) ? v0 : (u == 1) ? v1 : v2;
        float4 wv = *(const float4*)(w + c);
        float4 bv = *(const float4*)(bb + c);
        float o0 = (v.x - m) * inv * wv.x + bv.x;
        float o1 = (v.y - m) * inv * wv.y + bv.y;
        float o2 = (v.z - m) * inv * wv.z + bv.z;
        float o3 = (v.w - m) * inv * wv.w + bv.w;
        float h0 = __bfloat162float(__float2bfloat16_rn(o0));
        float h1 = __bfloat162float(__float2bfloat16_rn(o1));
        float h2 = __bfloat162float(__float2bfloat16_rn(o2));
        float h3 = __bfloat162float(__float2bfloat16_rn(o3));
        int w2 = (int)(((size_t)gw * ND + c) / 2);
        oh[w2] = pack_bf(h0, h1);
        oh[w2 + 1] = pack_bf(h2, h3);
        ol[w2] = pack_bf(o0 - h0, o1 - h1);
        ol[w2 + 1] = pack_bf(o2 - h2, o3 - h3);
    }
}

__global__ void split_a(const float* __restrict__ ipw, const float* __restrict__ opw,
                        bf16* __restrict__ hi, bf16* __restrict__ lo) {
    int n = N_IPW + N_OPW;
    for (int i = blockIdx.x * blockDim.x + threadIdx.x; i < n; i += gridDim.x * blockDim.x) {
        float v;
        int o;
        if (i < N_IPW) { v = ipw[i]; o = OFF_IPW + i; }
        else { v = opw[i - N_IPW]; o = OFF_OPW + (i - N_IPW); }
        bf16 h = __float2bfloat16_rn(v);
        hi[o] = h;
        lo[o] = __float2bfloat16_rn(v - __bfloat162float(h));
    }
}
__global__ void split_b(const float* __restrict__ cw, const float* __restrict__ xpw,
                        const float* __restrict__ dtw, const float* __restrict__ hw1,
                        const float* __restrict__ hw2, bf16* __restrict__ hi,
                        bf16* __restrict__ lo) {
    int n = N_CW + N_XPW + N_DTW + N_HW1 + N_HW2;
    for (int i = blockIdx.x * blockDim.x + threadIdx.x; i < n; i += gridDim.x * blockDim.x) {
        float v;
        int o;
        int j = i;
        if (j < N_CW) { v = cw[j]; o = OFF_CW + j; }
        else if ((j -= N_CW) < N_XPW) { v = xpw[j]; o = OFF_XPW + j; }
        else if ((j -= N_XPW) < N_DTW) { v = dtw[j]; o = OFF_DTW + j; }
        else if ((j -= N_DTW) < N_HW1) { v = hw1[j]; o = OFF_HW1 + j; }
        else { j -= N_HW1; v = hw2[j]; o = OFF_HW2 + j; }
        bf16 h = __float2bfloat16_rn(v);
        hi[o] = h;
        lo[o] = __float2bfloat16_rn(v - __bfloat162float(h));
    }
}

__global__ void gather_patches(const float* __restrict__ x, bf16* __restrict__ ph,
                               bf16* __restrict__ pl, const float* __restrict__ cls,
                               const float* __restrict__ pos, float* __restrict__ h) {
    int idx = blockIdx.x * blockDim.x + threadIdx.x;
    if (idx >= NB * NW * 256) return;
    if (idx < NB * ND) {
        int b = idx / ND, d = idx % ND;
        h[(size_t)(b * NL) * ND + d] = cls[d] + pos[d];
    }
    int k = idx & 255;
    int bw = idx >> 8;
    int w = bw & (NW - 1);
    int b = bw >> 9;
    float v = x[b * (NT * NF) + (2 * w + (k & 1)) * NF + (k >> 1)];
    bf16 hh = __float2bfloat16_rn(v);
    ph[idx] = hh;
    pl[idx] = __float2bfloat16_rn(v - __bfloat162float(hh));
}

__global__ void conv1d_silu_kernel(const float* __restrict__ xz, const float* __restrict__ w,
                                   const float* __restrict__ bconv, float* __restrict__ xc,
                                   bf16* __restrict__ xch, bf16* __restrict__ xcl) {
    int c = blockIdx.x * blockDim.x + threadIdx.x;
    int l0 = blockIdx.y * 4;
    int b = blockIdx.z;
    float v[7];
#pragma unroll
    for (int j = 0; j < 7; j++) {
        int l = l0 - 3 + j;
        v[j] = (l >= 0 && l < NL) ? xz[((size_t)(b * NL + l)) * (2 * NDI) + c] : 0.f;
    }
    float4 wt = *(const float4*)(w + c * 4);
    float bc = bconv[c];
#pragma unroll
    for (int t = 0; t < 4; t++) {
        int l = l0 + t;
        if (l >= NL) break;
        float a = bc;
        a = fmaf(v[t], wt.x, a);
        a = fmaf(v[t + 1], wt.y, a);
        a = fmaf(v[t + 2], wt.z, a);
        a = fmaf(v[t + 3], wt.w, a);
        float o = a / (1.f + __expf(-a));
        size_t idx = ((size_t)(b * NL + l)) * NDI + c;
        xc[idx] = o;
        bf16 hh = __float2bfloat16_rn(o);
        xch[idx] = hh;
        xcl[idx] = __float2bfloat16_rn(o - __bfloat162float(hh));
    }
}

__global__ void scan_a(const float* __restrict__ dt, const float* __restrict__ xc,
                       const float* __restrict__ xdbl, const float* __restrict__ Alog,
                       float* __restrict__ ao, float* __restrict__ so) {
    int lane = threadIdx.x & 31;
    int warp = threadIdx.x >> 5;
    int n = lane & 15;
    int ch = lane >> 4;
    int b = blockIdx.y;
    int c = blockIdx.z;
    int d = blockIdx.x * 16 + warp * 2 + ch;
    const float negA = -__expf(Alog[d * NN + n]);
    float ap = 1.f, s = 0.f;
    int t0 = c * CLEN, t1 = min(NL, t0 + CLEN);
    for (int t = t0; t < t1; t++) {
        int row = b * NL + t;
        float dtv = dt[(size_t)row * NDI + d];
        float xv = xc[(size_t)row * NDI + d];
        float Bn = xdbl[(size_t)row * XPD + NDTR + n];
        float a = __expf(dtv * negA);
        s = fmaf(a, s, dtv * Bn * xv);
        ap *= a;
    }
    int o = ((b * CH + c) * NDI + d) * NN + n;
    ao[o] = ap;
    so[o] = s;
}

// scan_c with inline prefix: init computed by folding chunks 0..c-1 of (ao,so)
__global__ void scan_c(const float* __restrict__ dt, const float* __restrict__ xc,
                       const float* __restrict__ xdbl, const float* __restrict__ xz,
                       const float* __restrict__ Alog, const float* __restrict__ Dsk,
                       const float* __restrict__ ao, const float* __restrict__ so,
                       bf16* __restrict__ yh, bf16* __restrict__ yl) {
    int lane = threadIdx.x & 31;
    int warp = threadIdx.x >> 5;
    int n = lane & 15;
    int ch = lane >> 4;
    int b = blockIdx.y;
    int c = blockIdx.z;
    int d = blockIdx.x * 16 + warp * 2 + ch;
    const float negA = -__expf(Alog[d * NN + n]);
    const float dsk = Dsk[d];
    float s = 0.f;
    for (int cc = 0; cc < c; cc++) {
        int o = ((b * CH + cc) * NDI + d) * NN + n;
        s = so[o] + ao[o] * s;
    }
    int t0 = c * CLEN, t1 = min(NL, t0 + CLEN);
    for (int t = t0; t < t1; t++) {
        int row = b * NL + t;
        float dtv = dt[(size_t)row * NDI + d];
        float xv = xc[(size_t)row * NDI + d];
        float Bn = xdbl[(size_t)row * XPD + NDTR + n];
        float Cn = xdbl[(size_t)row * XPD + NDTR + NN + n];
        float a = __expf(dtv * negA);
        s = fmaf(a, s, dtv * Bn * xv);
        float p = s * Cn;
        p += __shfl_xor_sync(0xffffffffu, p, 8, 16);
        p += __shfl_xor_sync(0xffffffffu, p, 4, 16);
        p += __shfl_xor_sync(0xffffffffu, p, 2, 16);
        p += __shfl_xor_sync(0xffffffffu, p, 1, 16);
        if (n == 0) {
            float yv = fmaf(dsk, xv, p);
            float zv = xz[(size_t)row * (2 * NDI) + NDI + d];
            yv *= zv / (1.f + __expf(-zv));
            bf16 hh = __float2bfloat16_rn(yv);
            yh[(size_t)row * NDI + d] = hh;
            yl[(size_t)row * NDI + d] = __float2bfloat16_rn(yv - __bfloat162float(hh));
        }
    }
}

static inline int cdiv(int a, int b) { return (a + b - 1) / b; }

extern "C" void kernel_launch(void* const* d_in, const int* in_sizes, int n_in,
                              void* d_out, int out_size) {
    const float* x = (const float*)d_in[0];
    const float* conv_w = (const float*)d_in[1];
    const float* conv_b = (const float*)d_in[2];
    const float* cls_tok = (const float*)d_in[3];
    const float* pos = (const float*)d_in[4];
    const float* norm_w = (const float*)d_in[5];
    const float* norm_b = (const float*)d_in[6];
    const float* ipw = (const float*)d_in[7];
    const float* c1w = (const float*)d_in[8];
    const float* c1b = (const float*)d_in[9];
    const float* xpw = (const float*)d_in[10];
    const float* dtw = (const float*)d_in[11];
    const float* dtb = (const float*)d_in[12];
    const float* Alog = (const float*)d_in[13];
    const float* Dsk = (const float*)d_in[14];
    const float* opw = (const float*)d_in[15];
    const float* nfw = (const float*)d_in[16];
    const float* nfb = (const float*)d_in[17];
    const float* hw1 = (const float*)d_in[18];
    const float* hb1 = (const float*)d_in[19];
    const float* hw2 = (const float*)d_in[20];
    const float* hb2 = (const float*)d_in[21];

    float *h, *xz, *xc, *xdbl, *dt, *part, *sca, *scs;
    bf16 *pmh, *pml, *hnh, *hnl, *xch, *xcl, *xdh, *xdl, *yh, *yl, *h1h, *h1l, *wh, *wl;
    cudaGetSymbolAddress((void**)&h, g_h);
    cudaGetSymbolAddress((void**)&xz, g_xz);
    cudaGetSymbolAddress((void**)&xc, g_xc);
    cudaGetSymbolAddress((void**)&xdbl, g_xdbl);
    cudaGetSymbolAddress((void**)&dt, g_dt);
    cudaGetSymbolAddress((void**)&part, g_part);
    cudaGetSymbolAddress((void**)&sca, g_sc_a);
    cudaGetSymbolAddress((void**)&scs, g_sc_s);
    cudaGetSymbolAddress((void**)&pmh, g_pm_h);
    cudaGetSymbolAddress((void**)&pml, g_pm_l);
    cudaGetSymbolAddress((void**)&hnh, g_hn_h);
    cudaGetSymbolAddress((void**)&hnl, g_hn_l);
    cudaGetSymbolAddress((void**)&xch, g_xc_h);
    cudaGetSymbolAddress((void**)&xcl, g_xc_l);
    cudaGetSymbolAddress((void**)&xdh, g_xd_h);
    cudaGetSymbolAddress((void**)&xdl, g_xd_l);
    cudaGetSymbolAddress((void**)&yh, g_y_h);
    cudaGetSymbolAddress((void**)&yl, g_y_l);
    cudaGetSymbolAddress((void**)&h1h, g_h1_h);
    cudaGetSymbolAddress((void**)&h1l, g_h1_l);
    cudaGetSymbolAddress((void**)&wh, g_w_h);
    cudaGetSymbolAddress((void**)&wl, g_w_l);

    cudaFuncSetAttribute(bgemm64<0>, cudaFuncAttributeMaxDynamicSharedMemorySize, B64_SMEM);
    cudaFuncSetAttribute(bgemm64<4>, cudaFuncAttributeMaxDynamicSharedMemorySize, B64_SMEM);
    cudaFuncSetAttribute(bgemm64<5>, cudaFuncAttributeMaxDynamicSharedMemorySize, B64_SMEM);

    split_a<<<2048, 256>>>(ipw, opw, wh, wl);
    split_b<<<1024, 256>>>(conv_w, xpw, dtw, hw1, hw2, wh, wl);
    gather_patches<<<cdiv(NB * NW * 256, 256), 256>>>(x, pmh, pml, cls_tok, pos, h);
    bgemm64<5><<<dim3(6, 16, 1), 256, B64_SMEM>>>(
        pmh, pml, 256, wh + OFF_CW, wl + OFF_CW, 256, h, ND, 0, conv_b, pos,
        2048, ND, 256, 256);
    ln_kernel<<<cdiv(NBL * 32, 256), 256>>>(h, norm_w, norm_b,
                                            (uint32_t*)hnh, (uint32_t*)hnl, NBL);

    for (int i = 0; i < NDEPTH; i++) {
        bgemm64<0><<<dim3(24, 17, 1), 256, B64_SMEM>>>(
            hnh, hnl, ND, wh + OFF_IPW + (size_t)i * 2 * NDI * ND,
            wl + OFF_IPW + (size_t)i * 2 * NDI * ND, ND, xz, 2 * NDI, 0,
            nullptr, nullptr, NBL, 2 * NDI, ND, ND);
        conv1d_silu_kernel<<<dim3(3, cdiv(NL, 4), NB), 256>>>(
            xz, c1w + (size_t)i * NDI * 4, c1b + (size_t)i * NDI, xc, xch, xcl);
        bgemm64<0><<<dim3(1, 17, 6), 256, B64_SMEM>>>(
            xch, xcl, NDI, wh + OFF_XPW + (size_t)i * XPD * NDI,
            wl + OFF_XPW + (size_t)i * XPD * NDI, NDI, part, XPD,
            (long long)NBL * XPD, nullptr, nullptr, NBL, XPD, NDI, 128);
        reduce_k<0, 1, 1><<<cdiv(NBL * XPD / 4, 256), 256>>>(
            part, (long long)NBL * XPD, 6, xdbl, nullptr,
            (uint32_t*)xdh, (uint32_t*)xdl, NBL * XPD, XPD);
        bgemm64<4><<<dim3(12, 17, 1), 256, B64_SMEM>>>(
            xdh, xdl, XPD, wh + OFF_DTW + (size_t)i * NDI * NDTR,
            wl + OFF_DTW + (size_t)i * NDI * NDTR, NDTR, dt, NDI, 0,
            dtb + (size_t)i * NDI, nullptr, NBL, NDI, NDTR, NDTR);
        scan_a<<<dim3(NDI / 16, NB, CH), 256>>>(dt, xc, xdbl,
                                                Alog + (size_t)i * NDI * NN, sca, scs);
        scan_c<<<dim3(NDI / 16, NB, CH), 256>>>(dt, xc, xdbl, xz,
                                                Alog + (size_t)i * NDI * NN,
                                                Dsk + (size_t)i * NDI, sca, scs, yh, yl);
        bgemm64<0><<<dim3(6, 17, 2), 256, B64_SMEM>>>(
            yh, yl, NDI, wh + OFF_OPW + (size_t)i * ND * NDI,
            wl + OFF_OPW + (size_t)i * ND * NDI, NDI, part, ND,
            (long long)NBL * ND, nullptr, nullptr, NBL, ND, NDI, 384);
        const float* lw = (i + 1 < NDEPTH) ? (norm_w + (i + 1) * ND) : nfw;
        const float* lb = (i + 1 < NDEPTH) ? (norm_b + (i + 1) * ND) : nfb;
        fres_ln<<<cdiv(NBL * 32, 256), 256>>>(part, (long long)NBL * ND, lw, lb, h,
                                              (uint32_t*)hnh, (uint32_t*)hnl, NBL);
    }

    bgemm64<0><<<dim3(6, 17, 2), 256, B64_SMEM>>>(
        hnh, hnl, ND, wh + OFF_HW1, wl + OFF_HW1, ND, part, ND,
        (long long)NBL * ND, nullptr, nullptr, NBL, ND, ND, 192);
    reduce_k<3, 0, 1><<<cdiv(NBL * ND / 4, 256), 256>>>(
        part, (long long)NBL * ND, 2, nullptr, hb1,
        (uint32_t*)h1h, (uint32_t*)h1l, NBL * ND, ND);
    bgemm64<0><<<dim3(4, 17, 2), 256, B64_SMEM>>>(
        h1h, h1l, ND, wh + OFF_HW2, wl + OFF_HW2, ND, part, NHEAD,
        (long long)NBL * NHEAD, nullptr, nullptr, NBL, NHEAD, ND, 192);
    reduce_k<2, 1, 0><<<cdiv(NBL * NHEAD / 4, 256), 256>>>(
        part, (long long)NBL * NHEAD, 2, (float*)d_out, hb2, nullptr, nullptr,
        NBL * NHEAD, NHEAD);
}